// round 11
// baseline (speedup 1.0000x reference)
#include <cuda_runtime.h>
#include <cuda_bf16.h>

#define BATCH 8
#define NBOX 2048
#define MAXDET 100
#define THREADS 128
#define EPT 16
#define MIN_SIZE 25.0f
#define SCORE_THR 0.001f
#define CIOU 0.23076923f            // 0.3/1.3 : iou>0.3 <=> inter > CIOU*(A+B)
#define FULL 0xffffffffu

typedef unsigned long long u64;
typedef unsigned int u32;

__device__ __forceinline__ u64 pack_si(float s, int idx) {
    return ((u64)__float_as_uint(s) << 32) | (u32)(~idx);
}
__device__ __forceinline__ float ciou_area(float4 b) {
    return CIOU * ((b.z - b.x) * (b.w - b.y));
}
__device__ __forceinline__ float inter_of(float4 a, float4 b) {
    float ix = fminf(a.z, b.z) - fmaxf(a.x, b.x);
    float iy = fminf(a.w, b.w) - fmaxf(a.y, b.y);
    return fmaxf(ix, 0.f) * fmaxf(iy, 0.f);
}

// register compare-exchange: descending when dir, ascending when !dir
#define RCE(E, F, K)                                                     \
    do {                                                                 \
        bool _dir = (((E * 128) & (K)) == 0);  /* k-bit is an e-bit */   \
        u64 _x = val[E], _y = val[F];                                    \
        bool _sw = _dir ? (_x < _y) : (_x > _y);                         \
        if (_sw) { val[E] = _y; val[F] = _x; }                           \
    } while (0)

extern __shared__ char smem_raw[];
// sbox f4[2048] | skey u64[2048] | pbox f4[100] | cbox f4[32]
// pca f[100] | cca f[32] | sdead u32[4] | smat8 u8[32*4]
#define SMEM_BYTES (32768 + 16384 + 1600 + 512 + 400 + 128 + 16 + 128 + 64)

__global__ __launch_bounds__(THREADS, 1)
void nms_kernel(const float* __restrict__ boxes,
                const float* __restrict__ scores,
                float* __restrict__ out,
                int write_mask)
{
    float4* sbox = (float4*)smem_raw;
    u64*    skey = (u64*)(sbox + NBOX);
    float4* pbox = (float4*)(skey + NBOX);
    float4* cbox = pbox + MAXDET;
    float*  pca  = (float*)(cbox + 32);
    float*  cca  = pca + MAXDET;
    u32*    sdead = (u32*)(cca + 32);
    unsigned char* smat8 = (unsigned char*)(sdead + 4);
    u32*    smat32 = (u32*)smat8;

    const int img  = blockIdx.x;
    const int tid  = threadIdx.x;
    const int warp = tid >> 5;
    const int lane = tid & 31;

    // ---- load, validity filter, build keys (striped: idx = e*128 + tid) ----
    const float4* bp = (const float4*)(boxes + (size_t)img * NBOX * 4);
    const float*  sp = scores + (size_t)img * NBOX;
    u64 val[EPT];
    #pragma unroll
    for (int e = 0; e < EPT; e++) {
        int i = e * THREADS + tid;
        float4 b = bp[i];
        float  s = sp[i];
        float w = b.z - b.x;
        float h = b.w - b.y;
        bool valid = (w >= MIN_SIZE) && (h >= MIN_SIZE) && (s >= SCORE_THR);
        sbox[i] = b;
        val[e]  = valid ? pack_si(s, i) : 0ULL;
    }

    // ---- init output padding ----
    float* outr = out + (size_t)img * MAXDET * 5;
    float* outm = out + (size_t)BATCH * MAXDET * 5 + (size_t)img * MAXDET;
    #pragma unroll
    for (int i = tid; i < MAXDET; i += THREADS) {
        outr[i * 5 + 0] = (float)img;
        outr[i * 5 + 1] = 0.f;
        outr[i * 5 + 2] = 0.f;
        outr[i * 5 + 3] = 0.f;
        outr[i * 5 + 4] = 0.f;
        if (write_mask) outm[i] = 0.f;
    }

    // ================= striped bitonic sort (descending) =====================
    // idx bits: [0:4]=lane (shfl), [5:6]=warp (shared), [7:10]=e (register)
    #pragma unroll 1
    for (int k = 2; k <= NBOX; k <<= 1) {
        // --- register stages: j >= 128 (e-bit exchanges) ---
        #pragma unroll 1
        for (int j = k >> 1; j >= 128; j >>= 1) {
            int jb = j >> 7;
            if (jb == 8) {
                #pragma unroll
                for (int e = 0; e < 8; e++) RCE(e, e + 8, k);
            } else if (jb == 4) {
                #pragma unroll
                for (int g = 0; g < 2; g++)
                    #pragma unroll
                    for (int e = 0; e < 4; e++) RCE(g * 8 + e, g * 8 + e + 4, k);
            } else if (jb == 2) {
                #pragma unroll
                for (int g = 0; g < 4; g++)
                    #pragma unroll
                    for (int e = 0; e < 2; e++) RCE(g * 4 + e, g * 4 + e + 2, k);
            } else {
                #pragma unroll
                for (int g = 0; g < 8; g++) RCE(g * 2, g * 2 + 1, k);
            }
        }
        // --- shared stages: j in {64, 32} (warp-bit exchanges) ---
        {
            int jhi = (k >> 1) > 64 ? 64 : (k >> 1);
            #pragma unroll 1
            for (int j = jhi; j >= 32; j >>= 1) {
                #pragma unroll
                for (int e = 0; e < EPT; e++) skey[e * THREADS + tid] = val[e];
                __syncthreads();
                bool iLow = ((tid & j) == 0);
                #pragma unroll
                for (int e = 0; e < EPT; e++) {
                    int idx = e * THREADS + tid;
                    u64 other = skey[idx ^ j];
                    bool dir = ((idx & k) == 0);
                    u64 mx = val[e] > other ? val[e] : other;
                    u64 mn = val[e] > other ? other : val[e];
                    val[e] = (iLow == dir) ? mx : mn;
                }
                __syncthreads();
            }
        }
        // --- shfl stages: j <= 16 (lane-bit exchanges) ---
        {
            int jhi = (k >> 1) > 16 ? 16 : (k >> 1);
            #pragma unroll 1
            for (int j = jhi; j >= 1; j >>= 1) {
                bool iLow = ((lane & j) == 0);
                #pragma unroll
                for (int e = 0; e < EPT; e++) {
                    int idx = e * THREADS + tid;
                    u64 other = __shfl_xor_sync(FULL, val[e], j);
                    bool dir = ((idx & k) == 0);
                    u64 mx = val[e] > other ? val[e] : other;
                    u64 mn = val[e] > other ? other : val[e];
                    val[e] = (iLow == dir) ? mx : mn;
                }
            }
        }
    }
    // write sorted keys (rank order) to shared
    #pragma unroll
    for (int e = 0; e < EPT; e++) skey[e * THREADS + tid] = val[e];
    __syncthreads();

    // ================= lazy greedy: batch-verified walk in rank order ========
    int npicks = 0;
    int rb = 0;
    while (rb < NBOX && npicks < MAXDET) {
        if (skey[rb] == 0ULL) break;           // all remaining invalid (uniform)

        if (tid < 32) {
            u64 kkey = skey[rb + tid];
            int idx = (int)(~(u32)kkey) & (NBOX - 1);
            float4 b = sbox[idx];
            cbox[tid] = b;
            cca[tid]  = ciou_area(b);
        }
        __syncthreads();

        float4 myb = cbox[lane];               // candidate = lane
        float  mya = cca[lane];

        // (a) candidate vs existing picks (picks strided over 4 warps)
        bool dead = false;
        for (int j = warp; j < npicks; j += 4) {
            float4 pb = pbox[j];
            dead |= inter_of(pb, myb) > pca[j] + mya;
        }
        u32 bal = __ballot_sync(FULL, dead);
        if (lane == 0) sdead[warp] = bal;

        // (b) 32x32 pairwise overlap matrix: row=lane, cols warp*8..warp*8+7
        u32 bits8 = 0;
        #pragma unroll
        for (int q = 0; q < 8; q++) {
            int c = warp * 8 + q;
            float4 ob = cbox[c];
            bool ov = inter_of(myb, ob) > mya + cca[c];
            bits8 |= (ov ? 1u : 0u) << q;
        }
        smat8[lane * 4 + warp] = (unsigned char)bits8;
        __syncthreads();

        u32 deadP = sdead[0] | sdead[1] | sdead[2] | sdead[3];

        // (c) exact in-batch greedy walk (redundant, uniform across threads)
        u32 acc = 0;
        #pragma unroll
        for (int j = 0; j < 32; j++) {
            u64 kj  = skey[rb + j];
            u32 row = smat32[j];
            bool take = (kj != 0ULL) && !((deadP >> j) & 1u) && ((acc & row) == 0u);
            if (take) acc |= 1u << j;
        }

        // (d) append accepted picks + write output rows
        if (tid < 32 && ((acc >> tid) & 1u)) {
            int slot = npicks + __popc(acc & ((1u << tid) - 1u));
            if (slot < MAXDET) {
                float4 b = cbox[tid];
                pbox[slot] = b;
                pca[slot]  = cca[tid];
                float* row = outr + slot * 5;
                row[1] = b.x; row[2] = b.y; row[3] = b.z; row[4] = b.w;
                if (write_mask) outm[slot] = 1.f;
            }
        }
        npicks = min(npicks + __popc(acc), MAXDET);
        rb += 32;
        __syncthreads();
    }
}

extern "C" void kernel_launch(void* const* d_in, const int* in_sizes, int n_in,
                              void* d_out, int out_size) {
    const float* boxes  = (const float*)d_in[0];   // [8,2048,4] f32
    const float* scores = (const float*)d_in[1];   // [8,2048]   f32
    float* out = (float*)d_out;
    int write_mask = (out_size >= BATCH * MAXDET * 5 + BATCH * MAXDET) ? 1 : 0;

    static int attr_done = 0;
    if (!attr_done) {
        cudaFuncSetAttribute(nms_kernel,
                             cudaFuncAttributeMaxDynamicSharedMemorySize,
                             SMEM_BYTES);
        attr_done = 1;
    }
    nms_kernel<<<BATCH, THREADS, SMEM_BYTES>>>(boxes, scores, out, write_mask);
}

// round 12
// speedup vs baseline: 1.1860x; 1.1860x over previous
#include <cuda_runtime.h>
#include <cuda_bf16.h>

#define BATCH 8
#define NBOX 2048
#define MAXDET 100
#define THREADS 128
#define EPT 16                      // sort: elements per thread (blocked)
#define MIN_SIZE 25.0f
#define SCORE_THR 0.001f
#define CIOU 0.23076923f            // 0.3/1.3 : iou>0.3 <=> inter > CIOU*(A+B)
#define FULL 0xffffffffu

typedef unsigned long long u64;
typedef unsigned int u32;

// key: (score bits << 32) | ~idx  -> descending sort == (score desc, idx asc)
__device__ __forceinline__ u64 pack_si(float s, int idx) {
    return ((u64)__float_as_uint(s) << 32) | (u32)(~idx);
}
__device__ __forceinline__ float ciou_area(float4 b) {
    return CIOU * ((b.z - b.x) * (b.w - b.y));
}
__device__ __forceinline__ float inter_of(float4 a, float4 b) {
    float ix = fminf(a.z, b.z) - fmaxf(a.x, b.x);
    float iy = fminf(a.w, b.w) - fmaxf(a.y, b.y);
    return fmaxf(ix, 0.f) * fmaxf(iy, 0.f);
}

extern __shared__ char smem_raw[];
// sbox f4[2048] | skey u64[2048] | pbox f4[100] | cbox f4[32]
// pca f[100] | cca f[32] | sdead u32[4] | svalid u32 | smat8 u8[32*4]
#define SMEM_BYTES (32768 + 16384 + 1600 + 512 + 400 + 128 + 16 + 16 + 128 + 64)

__global__ __launch_bounds__(THREADS, 1)
void nms_kernel(const float* __restrict__ boxes,
                const float* __restrict__ scores,
                float* __restrict__ out,
                int write_mask)
{
    float4* sbox = (float4*)smem_raw;
    u64*    skey = (u64*)(sbox + NBOX);
    float4* pbox = (float4*)(skey + NBOX);
    float4* cbox = pbox + MAXDET;
    float*  pca  = (float*)(cbox + 32);
    float*  cca  = pca + MAXDET;
    u32*    sdead = (u32*)(cca + 32);
    u32*    svalid = sdead + 4;
    unsigned char* smat8 = (unsigned char*)(svalid + 4);
    u32*    smat32 = (u32*)smat8;

    const int img  = blockIdx.x;
    const int tid  = threadIdx.x;
    const int warp = tid >> 5;
    const int lane = tid & 31;
    const int base = tid * EPT;

    // ---- load, validity filter, build keys (invalid -> 0) ----
    const float4* bp = (const float4*)(boxes + (size_t)img * NBOX * 4);
    const float*  sp = scores + (size_t)img * NBOX;
    #pragma unroll
    for (int p = 0; p < NBOX / THREADS; p++) {
        int i = p * THREADS + tid;
        float4 b = bp[i];
        float  s = sp[i];
        float w = b.z - b.x;
        float h = b.w - b.y;
        bool valid = (w >= MIN_SIZE) && (h >= MIN_SIZE) && (s >= SCORE_THR);
        sbox[i] = b;
        skey[i] = valid ? pack_si(s, i) : 0ULL;
    }

    // ---- init output padding: [img,0,0,0,0] rows, mask = 0 ----
    float* outr = out + (size_t)img * MAXDET * 5;
    float* outm = out + (size_t)BATCH * MAXDET * 5 + (size_t)img * MAXDET;
    #pragma unroll
    for (int i = tid; i < MAXDET; i += THREADS) {
        outr[i * 5 + 0] = (float)img;
        outr[i * 5 + 1] = 0.f;
        outr[i * 5 + 2] = 0.f;
        outr[i * 5 + 3] = 0.f;
        outr[i * 5 + 4] = 0.f;
        if (write_mask) outm[i] = 0.f;
    }
    __syncthreads();

    // ================= bitonic sort (descending), blocked-register hybrid ====
    u64 key[EPT];
    #pragma unroll
    for (int e = 0; e < EPT; e++) key[e] = skey[base + e];

    // presort k=2..16 entirely in registers
    #pragma unroll
    for (int k = 2; k <= 16; k <<= 1) {
        #pragma unroll
        for (int j = k >> 1; j > 0; j >>= 1) {
            #pragma unroll
            for (int e = 0; e < EPT; e++) {
                if ((e & j) == 0) {
                    int f = e | j;
                    bool up = (((base + e) & k) == 0);
                    u64 x = key[e], y = key[f];
                    bool sw = up ? (x < y) : (x > y);
                    if (sw) { key[e] = y; key[f] = x; }
                }
            }
        }
    }

    // k-phases 32..2048: shared stages for j>=16, register tail j<=8
    #pragma unroll 1
    for (int kk = 32; kk <= NBOX; kk <<= 1) {
        #pragma unroll
        for (int e = 0; e < EPT; e++) skey[base + e] = key[e];
        __syncthreads();
        #pragma unroll 1
        for (int j = kk >> 1; j >= 16; j >>= 1) {
            #pragma unroll
            for (int n = 0; n < NBOX / 2 / THREADS; n++) {
                int idx = tid + n * THREADS;
                int i1 = ((idx & ~(j - 1)) << 1) | (idx & (j - 1));
                int i2 = i1 | j;
                bool up = ((i1 & kk) == 0);
                u64 x = skey[i1], y = skey[i2];
                bool sw = up ? (x < y) : (x > y);
                if (sw) { skey[i1] = y; skey[i2] = x; }
            }
            __syncthreads();
        }
        #pragma unroll
        for (int e = 0; e < EPT; e++) key[e] = skey[base + e];
        {
            bool up = ((base & kk) == 0);
            #pragma unroll
            for (int j = 8; j > 0; j >>= 1) {
                #pragma unroll
                for (int e = 0; e < EPT; e++) {
                    if ((e & j) == 0) {
                        int f = e | j;
                        u64 x = key[e], y = key[f];
                        bool sw = up ? (x < y) : (x > y);
                        if (sw) { key[e] = y; key[f] = x; }
                    }
                }
            }
        }
    }
    // final write-back: sorted keys to shared for the batch engine
    #pragma unroll
    for (int e = 0; e < EPT; e++) skey[base + e] = key[e];
    __syncthreads();

    // ================= lazy greedy: batch-verified walk in rank order ========
    int npicks = 0;
    int rb = 0;
    while (rb < NBOX && npicks < MAXDET) {
        if (skey[rb] == 0ULL) break;           // all remaining invalid (uniform)

        // stage candidate boxes (ranks rb..rb+31) + validity ballot (warp 0)
        if (warp == 0) {
            u64 kkey = skey[rb + lane];
            int idx = (int)(~(u32)kkey) & (NBOX - 1);
            float4 b = sbox[idx];
            cbox[lane] = b;
            cca[lane]  = ciou_area(b);
            u32 vb = __ballot_sync(FULL, kkey != 0ULL);
            if (lane == 0) *svalid = vb;
        }
        __syncthreads();

        float4 myb = cbox[lane];               // candidate = lane
        float  mya = cca[lane];

        // (a) candidate vs existing picks (picks strided over 4 warps)
        bool dead = false;
        for (int j = warp; j < npicks; j += 4) {
            float4 pb = pbox[j];
            dead |= inter_of(pb, myb) > pca[j] + mya;
        }
        u32 bal = __ballot_sync(FULL, dead);
        if (lane == 0) sdead[warp] = bal;

        // (b) 32x32 pairwise overlap matrix: row=lane, cols warp*8..warp*8+7
        u32 bits8 = 0;
        #pragma unroll
        for (int q = 0; q < 8; q++) {
            int c = warp * 8 + q;
            float4 ob = cbox[c];
            bool ov = inter_of(myb, ob) > mya + cca[c];
            bits8 |= (ov ? 1u : 0u) << q;
        }
        smat8[lane * 4 + warp] = (unsigned char)bits8;
        __syncthreads();

        u32 deadP = sdead[0] | sdead[1] | sdead[2] | sdead[3];
        u32 vmask = *svalid;
        u32 elig  = vmask & ~deadP;            // eligible candidates

        // (c) exact in-batch greedy walk — rows preloaded, pure-ALU chain
        u32 rows[32];
        #pragma unroll
        for (int j = 0; j < 32; j++) rows[j] = smat32[j];
        u32 acc = 0;
        #pragma unroll
        for (int j = 0; j < 32; j++) {
            bool take = ((elig >> j) & 1u) && ((acc & rows[j]) == 0u);
            acc |= (take ? 1u : 0u) << j;
        }

        // (d) append accepted picks + write output rows
        if (tid < 32 && ((acc >> tid) & 1u)) {
            int slot = npicks + __popc(acc & ((1u << tid) - 1u));
            if (slot < MAXDET) {
                float4 b = cbox[tid];
                pbox[slot] = b;
                pca[slot]  = cca[tid];
                float* row = outr + slot * 5;
                row[1] = b.x; row[2] = b.y; row[3] = b.z; row[4] = b.w;
                if (write_mask) outm[slot] = 1.f;
            }
        }
        npicks = min(npicks + __popc(acc), MAXDET);
        rb += 32;
        __syncthreads();
    }
}

extern "C" void kernel_launch(void* const* d_in, const int* in_sizes, int n_in,
                              void* d_out, int out_size) {
    const float* boxes  = (const float*)d_in[0];   // [8,2048,4] f32
    const float* scores = (const float*)d_in[1];   // [8,2048]   f32
    float* out = (float*)d_out;
    int write_mask = (out_size >= BATCH * MAXDET * 5 + BATCH * MAXDET) ? 1 : 0;

    static int attr_done = 0;
    if (!attr_done) {
        cudaFuncSetAttribute(nms_kernel,
                             cudaFuncAttributeMaxDynamicSharedMemorySize,
                             SMEM_BYTES);
        attr_done = 1;
    }
    nms_kernel<<<BATCH, THREADS, SMEM_BYTES>>>(boxes, scores, out, write_mask);
}

// round 13
// speedup vs baseline: 1.4735x; 1.2424x over previous
#include <cuda_runtime.h>
#include <cuda_bf16.h>

#define BATCH 8
#define NBOX 2048
#define MAXDET 100
#define THREADS 128
#define EPT 16                      // sort: elements per thread (blocked)
#define MIN_SIZE 25.0f
#define SCORE_THR 0.001f
#define CIOU 0.23076923f            // 0.3/1.3 : iou>0.3 <=> inter > CIOU*(A+B)
#define FULL 0xffffffffu

typedef unsigned long long u64;
typedef unsigned int u32;

// key: (score bits << 32) | ~idx  -> descending sort == (score desc, idx asc)
__device__ __forceinline__ u64 pack_si(float s, int idx) {
    return ((u64)__float_as_uint(s) << 32) | (u32)(~idx);
}
__device__ __forceinline__ float ciou_area(float4 b) {
    return CIOU * ((b.z - b.x) * (b.w - b.y));
}
__device__ __forceinline__ float inter_of(float4 a, float4 b) {
    float ix = fminf(a.z, b.z) - fmaxf(a.x, b.x);
    float iy = fminf(a.w, b.w) - fmaxf(a.y, b.y);
    return fmaxf(ix, 0.f) * fmaxf(iy, 0.f);
}

extern __shared__ char smem_raw[];
// sbox f4[2048] | skey u64[2048] | pbox f4[100] | cbox f4[32]
// pca f[100] | cca f[32] | sdead u32[4] | svalid u32 | smat8 u8[32*4]
#define SMEM_BYTES (32768 + 16384 + 1600 + 512 + 400 + 128 + 16 + 16 + 128 + 64)

__global__ __launch_bounds__(THREADS, 1)
void nms_kernel(const float* __restrict__ boxes,
                const float* __restrict__ scores,
                float* __restrict__ out,
                int write_mask)
{
    float4* sbox = (float4*)smem_raw;
    u64*    skey = (u64*)(sbox + NBOX);
    float4* pbox = (float4*)(skey + NBOX);
    float4* cbox = pbox + MAXDET;
    float*  pca  = (float*)(cbox + 32);
    float*  cca  = pca + MAXDET;
    u32*    sdead = (u32*)(cca + 32);
    u32*    svalid = sdead + 4;
    unsigned char* smat8 = (unsigned char*)(svalid + 4);
    u32*    smat32 = (u32*)smat8;

    const int img  = blockIdx.x;
    const int tid  = threadIdx.x;
    const int warp = tid >> 5;
    const int lane = tid & 31;
    const int base = tid * EPT;

    // ---- load, validity filter, build keys directly into registers ----
    const float4* bp = (const float4*)(boxes + (size_t)img * NBOX * 4);
    const float*  sp = scores + (size_t)img * NBOX;
    u64 val[EPT];
    #pragma unroll
    for (int e = 0; e < EPT; e++) {
        int i = base + e;                    // blocked ownership
        float4 b = bp[i];
        float  s = sp[i];
        float w = b.z - b.x;
        float h = b.w - b.y;
        bool valid = (w >= MIN_SIZE) && (h >= MIN_SIZE) && (s >= SCORE_THR);
        sbox[i] = b;
        val[e]  = valid ? pack_si(s, i) : 0ULL;
    }

    // ---- init output padding: [img,0,0,0,0] rows, mask = 0 ----
    float* outr = out + (size_t)img * MAXDET * 5;
    float* outm = out + (size_t)BATCH * MAXDET * 5 + (size_t)img * MAXDET;
    #pragma unroll
    for (int i = tid; i < MAXDET; i += THREADS) {
        outr[i * 5 + 0] = (float)img;
        outr[i * 5 + 1] = 0.f;
        outr[i * 5 + 2] = 0.f;
        outr[i * 5 + 3] = 0.f;
        outr[i * 5 + 4] = 0.f;
        if (write_mask) outm[i] = 0.f;
    }

    // ================= bitonic sort (descending) =============================
    // blocked layout: idx = tid*16 + e. bits: [0:3]=e (regs),
    // [4:8]=lane bits (j=16..256 -> shfl), [9:10]=warp bits (j=512/1024 -> smem)

    // presort k=2..16 entirely in registers
    #pragma unroll
    for (int k = 2; k <= 16; k <<= 1) {
        #pragma unroll
        for (int j = k >> 1; j > 0; j >>= 1) {
            #pragma unroll
            for (int e = 0; e < EPT; e++) {
                if ((e & j) == 0) {
                    int f = e | j;
                    bool up = (((base + e) & k) == 0);
                    u64 x = val[e], y = val[f];
                    bool sw = up ? (x < y) : (x > y);
                    if (sw) { val[e] = y; val[f] = x; }
                }
            }
        }
    }

    #pragma unroll 1
    for (int kk = 32; kk <= NBOX; kk <<= 1) {
        const bool dir = ((base & kk) == 0);          // uniform over e (kk>=32)

        // --- shared stages: j in {1024, 512} (warp-bit exchanges) ---
        #pragma unroll 1
        for (int j = kk >> 1; j >= 512; j >>= 1) {
            #pragma unroll
            for (int e = 0; e < EPT; e++) skey[base + e] = val[e];
            __syncthreads();
            bool iLow = ((tid & (j >> 4)) == 0);
            int pbase = base ^ j;                     // partner thread's block
            #pragma unroll
            for (int e = 0; e < EPT; e++) {
                u64 o = skey[pbase + e];
                u64 mx = val[e] > o ? val[e] : o;
                u64 mn = val[e] > o ? o : val[e];
                val[e] = (iLow == dir) ? mx : mn;
            }
            __syncthreads();
        }

        // --- shfl stages: j in {256..16} (lane-bit exchanges) ---
        {
            int jhi = (kk >> 1) > 256 ? 256 : (kk >> 1);
            #pragma unroll 1
            for (int j = jhi; j >= 16; j >>= 1) {
                int jl = j >> 4;                      // lane xor mask
                bool iLow = ((tid & jl) == 0);
                #pragma unroll
                for (int e = 0; e < EPT; e++) {
                    u64 o = __shfl_xor_sync(FULL, val[e], jl);
                    u64 mx = val[e] > o ? val[e] : o;
                    u64 mn = val[e] > o ? o : val[e];
                    val[e] = (iLow == dir) ? mx : mn;
                }
            }
        }

        // --- register tail: j = 8..1 ---
        #pragma unroll
        for (int j = 8; j > 0; j >>= 1) {
            #pragma unroll
            for (int e = 0; e < EPT; e++) {
                if ((e & j) == 0) {
                    int f = e | j;
                    u64 x = val[e], y = val[f];
                    bool sw = dir ? (x < y) : (x > y);
                    if (sw) { val[e] = y; val[f] = x; }
                }
            }
        }
    }
    // write sorted keys (rank order) to shared for the batch engine
    #pragma unroll
    for (int e = 0; e < EPT; e++) skey[base + e] = val[e];
    __syncthreads();

    // ================= lazy greedy: batch-verified walk in rank order ========
    int npicks = 0;
    int rb = 0;
    while (rb < NBOX && npicks < MAXDET) {
        if (skey[rb] == 0ULL) break;           // all remaining invalid (uniform)

        // stage candidate boxes (ranks rb..rb+31) + validity ballot (warp 0)
        if (warp == 0) {
            u64 kkey = skey[rb + lane];
            int idx = (int)(~(u32)kkey) & (NBOX - 1);
            float4 b = sbox[idx];
            cbox[lane] = b;
            cca[lane]  = ciou_area(b);
            u32 vb = __ballot_sync(FULL, kkey != 0ULL);
            if (lane == 0) *svalid = vb;
        }
        __syncthreads();

        float4 myb = cbox[lane];               // candidate = lane
        float  mya = cca[lane];

        // (a) candidate vs existing picks (picks strided over 4 warps)
        bool dead = false;
        for (int j = warp; j < npicks; j += 4) {
            float4 pb = pbox[j];
            dead |= inter_of(pb, myb) > pca[j] + mya;
        }
        u32 bal = __ballot_sync(FULL, dead);
        if (lane == 0) sdead[warp] = bal;

        // (b) 32x32 pairwise overlap matrix: row=lane, cols warp*8..warp*8+7
        u32 bits8 = 0;
        #pragma unroll
        for (int q = 0; q < 8; q++) {
            int c = warp * 8 + q;
            float4 ob = cbox[c];
            bool ov = inter_of(myb, ob) > mya + cca[c];
            bits8 |= (ov ? 1u : 0u) << q;
        }
        smat8[lane * 4 + warp] = (unsigned char)bits8;
        __syncthreads();

        u32 deadP = sdead[0] | sdead[1] | sdead[2] | sdead[3];
        u32 elig  = *svalid & ~deadP;          // eligible candidates

        // (c) exact in-batch greedy walk — rows preloaded, pure-ALU chain
        u32 rows[32];
        #pragma unroll
        for (int j = 0; j < 32; j++) rows[j] = smat32[j];
        u32 acc = 0;
        #pragma unroll
        for (int j = 0; j < 32; j++) {
            bool take = ((elig >> j) & 1u) && ((acc & rows[j]) == 0u);
            acc |= (take ? 1u : 0u) << j;
        }

        // (d) append accepted picks + write output rows
        if (tid < 32 && ((acc >> tid) & 1u)) {
            int slot = npicks + __popc(acc & ((1u << tid) - 1u));
            if (slot < MAXDET) {
                float4 b = cbox[tid];
                pbox[slot] = b;
                pca[slot]  = cca[tid];
                float* row = outr + slot * 5;
                row[1] = b.x; row[2] = b.y; row[3] = b.z; row[4] = b.w;
                if (write_mask) outm[slot] = 1.f;
            }
        }
        npicks = min(npicks + __popc(acc), MAXDET);
        rb += 32;
        __syncthreads();
    }
}

extern "C" void kernel_launch(void* const* d_in, const int* in_sizes, int n_in,
                              void* d_out, int out_size) {
    const float* boxes  = (const float*)d_in[0];   // [8,2048,4] f32
    const float* scores = (const float*)d_in[1];   // [8,2048]   f32
    float* out = (float*)d_out;
    int write_mask = (out_size >= BATCH * MAXDET * 5 + BATCH * MAXDET) ? 1 : 0;

    static int attr_done = 0;
    if (!attr_done) {
        cudaFuncSetAttribute(nms_kernel,
                             cudaFuncAttributeMaxDynamicSharedMemorySize,
                             SMEM_BYTES);
        attr_done = 1;
    }
    nms_kernel<<<BATCH, THREADS, SMEM_BYTES>>>(boxes, scores, out, write_mask);
}

// round 14
// speedup vs baseline: 1.4753x; 1.0013x over previous
#include <cuda_runtime.h>
#include <cuda_bf16.h>

#define BATCH 8
#define NBOX 2048
#define MAXDET 100
#define THREADS 128
#define EPT 16                      // sort: elements per thread (blocked)
#define MIN_SIZE 25.0f
#define SCORE_THR 0.001f
#define CIOU 0.23076923f            // 0.3/1.3 : iou>0.3 <=> inter > CIOU*(A+B)
#define FULL 0xffffffffu

typedef unsigned long long u64;
typedef unsigned int u32;

// key: (score bits << 32) | ~idx  -> descending sort == (score desc, idx asc)
__device__ __forceinline__ u64 pack_si(float s, int idx) {
    return ((u64)__float_as_uint(s) << 32) | (u32)(~idx);
}
__device__ __forceinline__ float ciou_area(float4 b) {
    return CIOU * ((b.z - b.x) * (b.w - b.y));
}
__device__ __forceinline__ float inter_of(float4 a, float4 b) {
    float ix = fminf(a.z, b.z) - fmaxf(a.x, b.x);
    float iy = fminf(a.w, b.w) - fmaxf(a.y, b.y);
    return fmaxf(ix, 0.f) * fmaxf(iy, 0.f);
}

extern __shared__ char smem_raw[];
// sbox f4[2048] | skey u64[2048] | pbox f4[100] | pca f[100]
// sdead u32[4] | smat8 u8[32*4]
#define SMEM_BYTES (32768 + 16384 + 1600 + 400 + 16 + 128 + 64)

__global__ __launch_bounds__(THREADS, 1)
void nms_kernel(const float* __restrict__ boxes,
                const float* __restrict__ scores,
                float* __restrict__ out,
                int write_mask)
{
    float4* sbox = (float4*)smem_raw;
    u64*    skey = (u64*)(sbox + NBOX);
    float4* pbox = (float4*)(skey + NBOX);
    float*  pca  = (float*)(pbox + MAXDET);
    u32*    sdead = (u32*)(pca + MAXDET);
    unsigned char* smat8 = (unsigned char*)(sdead + 4);
    u32*    smat32 = (u32*)smat8;

    const int img  = blockIdx.x;
    const int tid  = threadIdx.x;
    const int warp = tid >> 5;
    const int lane = tid & 31;
    const int base = tid * EPT;

    // ---- coalesced load, validity filter, keys to shared ----
    const float4* bp = (const float4*)(boxes + (size_t)img * NBOX * 4);
    const float*  sp = scores + (size_t)img * NBOX;
    #pragma unroll
    for (int p = 0; p < NBOX / THREADS; p++) {
        int i = p * THREADS + tid;               // coalesced
        float4 b = bp[i];
        float  s = sp[i];
        float w = b.z - b.x;
        float h = b.w - b.y;
        bool valid = (w >= MIN_SIZE) && (h >= MIN_SIZE) && (s >= SCORE_THR);
        sbox[i] = b;
        skey[i] = valid ? pack_si(s, i) : 0ULL;
    }

    // ---- init output padding: [img,0,0,0,0] rows, mask = 0 ----
    float* outr = out + (size_t)img * MAXDET * 5;
    float* outm = out + (size_t)BATCH * MAXDET * 5 + (size_t)img * MAXDET;
    #pragma unroll
    for (int i = tid; i < MAXDET; i += THREADS) {
        outr[i * 5 + 0] = (float)img;
        outr[i * 5 + 1] = 0.f;
        outr[i * 5 + 2] = 0.f;
        outr[i * 5 + 3] = 0.f;
        outr[i * 5 + 4] = 0.f;
        if (write_mask) outm[i] = 0.f;
    }
    __syncthreads();

    // blocked ownership for the sort
    u64 val[EPT];
    #pragma unroll
    for (int e = 0; e < EPT; e++) val[e] = skey[base + e];

    // ================= bitonic sort (descending) =============================
    // blocked layout: idx = tid*16 + e. bits: [0:3]=e (regs),
    // [4:8]=lane bits (j=16..256 -> shfl), [9:10]=warp bits (j=512/1024 -> smem)

    // presort k=2..16 entirely in registers
    #pragma unroll
    for (int k = 2; k <= 16; k <<= 1) {
        #pragma unroll
        for (int j = k >> 1; j > 0; j >>= 1) {
            #pragma unroll
            for (int e = 0; e < EPT; e++) {
                if ((e & j) == 0) {
                    int f = e | j;
                    bool up = (((base + e) & k) == 0);
                    u64 x = val[e], y = val[f];
                    bool sw = up ? (x < y) : (x > y);
                    if (sw) { val[e] = y; val[f] = x; }
                }
            }
        }
    }

    #pragma unroll 1
    for (int kk = 32; kk <= NBOX; kk <<= 1) {
        const bool dir = ((base & kk) == 0);          // uniform over e (kk>=32)

        // --- shared stages: j in {1024, 512} (warp-bit exchanges) ---
        #pragma unroll 1
        for (int j = kk >> 1; j >= 512; j >>= 1) {
            #pragma unroll
            for (int e = 0; e < EPT; e++) skey[base + e] = val[e];
            __syncthreads();
            bool iLow = ((tid & (j >> 4)) == 0);
            int pbase = base ^ j;                     // partner thread's block
            #pragma unroll
            for (int e = 0; e < EPT; e++) {
                u64 o = skey[pbase + e];
                u64 mx = val[e] > o ? val[e] : o;
                u64 mn = val[e] > o ? o : val[e];
                val[e] = (iLow == dir) ? mx : mn;
            }
            __syncthreads();
        }

        // --- shfl stages: j in {256..16} (lane-bit exchanges) ---
        {
            int jhi = (kk >> 1) > 256 ? 256 : (kk >> 1);
            #pragma unroll 1
            for (int j = jhi; j >= 16; j >>= 1) {
                int jl = j >> 4;                      // lane xor mask
                bool iLow = ((tid & jl) == 0);
                #pragma unroll
                for (int e = 0; e < EPT; e++) {
                    u64 o = __shfl_xor_sync(FULL, val[e], jl);
                    u64 mx = val[e] > o ? val[e] : o;
                    u64 mn = val[e] > o ? o : val[e];
                    val[e] = (iLow == dir) ? mx : mn;
                }
            }
        }

        // --- register tail: j = 8..1 ---
        #pragma unroll
        for (int j = 8; j > 0; j >>= 1) {
            #pragma unroll
            for (int e = 0; e < EPT; e++) {
                if ((e & j) == 0) {
                    int f = e | j;
                    u64 x = val[e], y = val[f];
                    bool sw = dir ? (x < y) : (x > y);
                    if (sw) { val[e] = y; val[f] = x; }
                }
            }
        }
    }
    // write sorted keys (rank order) to shared for the batch engine
    #pragma unroll
    for (int e = 0; e < EPT; e++) skey[base + e] = val[e];
    __syncthreads();

    // ================= lazy greedy: batch-verified walk in rank order ========
    int npicks = 0;
    int rb = 0;
    while (rb < NBOX && npicks < MAXDET) {
        // stage candidates redundantly in every warp (broadcast LDS)
        u64 kkey = skey[rb + lane];
        if (__shfl_sync(FULL, kkey, 0) == 0ULL) break;   // rank rb invalid => done

        int cidx = (int)(~(u32)kkey) & (NBOX - 1);
        float4 myb = sbox[cidx];               // candidate = lane (all warps)
        float  mya = ciou_area(myb);
        u32 vmask = __ballot_sync(FULL, kkey != 0ULL);   // identical per warp

        // (a) candidate vs existing picks (picks strided over 4 warps)
        bool dead = false;
        for (int j = warp; j < npicks; j += 4) {
            float4 pb = pbox[j];
            dead |= inter_of(pb, myb) > pca[j] + mya;
        }
        u32 bal = __ballot_sync(FULL, dead);
        if (lane == 0) sdead[warp] = bal;

        // (b) 32x32 pairwise overlap: partner boxes via shfl from lane c
        u32 bits8 = 0;
        #pragma unroll
        for (int q = 0; q < 8; q++) {
            int c = warp * 8 + q;
            float4 ob;
            ob.x = __shfl_sync(FULL, myb.x, c);
            ob.y = __shfl_sync(FULL, myb.y, c);
            ob.z = __shfl_sync(FULL, myb.z, c);
            ob.w = __shfl_sync(FULL, myb.w, c);
            float oa = __shfl_sync(FULL, mya, c);
            bool ov = inter_of(myb, ob) > mya + oa;
            bits8 |= (ov ? 1u : 0u) << q;
        }
        smat8[lane * 4 + warp] = (unsigned char)bits8;
        __syncthreads();

        u32 deadP = sdead[0] | sdead[1] | sdead[2] | sdead[3];
        u32 elig  = vmask & ~deadP;            // eligible candidates

        // (c) exact in-batch greedy walk — rows preloaded, pure-ALU chain
        u32 rows[32];
        #pragma unroll
        for (int j = 0; j < 32; j++) rows[j] = smat32[j];
        u32 acc = 0;
        #pragma unroll
        for (int j = 0; j < 32; j++) {
            bool take = ((elig >> j) & 1u) && ((acc & rows[j]) == 0u);
            acc |= (take ? 1u : 0u) << j;
        }

        // (d) append accepted picks + write output rows (warp0: lane == candidate)
        if (tid < 32 && ((acc >> tid) & 1u)) {
            int slot = npicks + __popc(acc & ((1u << tid) - 1u));
            if (slot < MAXDET) {
                pbox[slot] = myb;
                pca[slot]  = mya;
                float* row = outr + slot * 5;
                row[1] = myb.x; row[2] = myb.y; row[3] = myb.z; row[4] = myb.w;
                if (write_mask) outm[slot] = 1.f;
            }
        }
        npicks = min(npicks + __popc(acc), MAXDET);
        rb += 32;
        __syncthreads();                       // pbox/pca + smat reuse
    }
}

extern "C" void kernel_launch(void* const* d_in, const int* in_sizes, int n_in,
                              void* d_out, int out_size) {
    const float* boxes  = (const float*)d_in[0];   // [8,2048,4] f32
    const float* scores = (const float*)d_in[1];   // [8,2048]   f32
    float* out = (float*)d_out;
    int write_mask = (out_size >= BATCH * MAXDET * 5 + BATCH * MAXDET) ? 1 : 0;

    static int attr_done = 0;
    if (!attr_done) {
        cudaFuncSetAttribute(nms_kernel,
                             cudaFuncAttributeMaxDynamicSharedMemorySize,
                             SMEM_BYTES);
        attr_done = 1;
    }
    nms_kernel<<<BATCH, THREADS, SMEM_BYTES>>>(boxes, scores, out, write_mask);
}

// round 15
// speedup vs baseline: 1.6231x; 1.1001x over previous
#include <cuda_runtime.h>
#include <cuda_bf16.h>

#define BATCH 8
#define NBOX 2048
#define MAXDET 100
#define THREADS 256
#define EPT 8                       // sort: elements per thread (blocked)
#define MIN_SIZE 25.0f
#define SCORE_THR 0.001f
#define CIOU 0.23076923f            // 0.3/1.3 : iou>0.3 <=> inter > CIOU*(A+B)
#define FULL 0xffffffffu

typedef unsigned long long u64;
typedef unsigned int u32;

// key: (score bits << 32) | ~idx  -> descending sort == (score desc, idx asc)
__device__ __forceinline__ u64 pack_si(float s, int idx) {
    return ((u64)__float_as_uint(s) << 32) | (u32)(~idx);
}
__device__ __forceinline__ float ciou_area(float4 b) {
    return CIOU * ((b.z - b.x) * (b.w - b.y));
}
__device__ __forceinline__ float inter_of(float4 a, float4 b) {
    float ix = fminf(a.z, b.z) - fmaxf(a.x, b.x);
    float iy = fminf(a.w, b.w) - fmaxf(a.y, b.y);
    return fmaxf(ix, 0.f) * fmaxf(iy, 0.f);
}

extern __shared__ char smem_raw[];
// sbox f4[2048] | skey u64[2048] | pbox f4[100] | pca f[100]
// sdead u32[4] | sacc u32 | smat8 u8[32*4]
#define SMEM_BYTES (32768 + 16384 + 1600 + 400 + 16 + 16 + 128 + 64)

__global__ __launch_bounds__(THREADS, 1)
void nms_kernel(const float* __restrict__ boxes,
                const float* __restrict__ scores,
                float* __restrict__ out,
                int write_mask)
{
    float4* sbox = (float4*)smem_raw;
    u64*    skey = (u64*)(sbox + NBOX);
    float4* pbox = (float4*)(skey + NBOX);
    float*  pca  = (float*)(pbox + MAXDET);
    u32*    sdead = (u32*)(pca + MAXDET);
    u32*    sacc  = sdead + 4;
    unsigned char* smat8 = (unsigned char*)(sacc + 4);
    u32*    smat32 = (u32*)smat8;

    const int img  = blockIdx.x;
    const int tid  = threadIdx.x;
    const int warp = tid >> 5;
    const int lane = tid & 31;
    const int base = tid * EPT;

    // ---- coalesced load, validity filter, keys to shared ----
    const float4* bp = (const float4*)(boxes + (size_t)img * NBOX * 4);
    const float*  sp = scores + (size_t)img * NBOX;
    #pragma unroll
    for (int p = 0; p < NBOX / THREADS; p++) {
        int i = p * THREADS + tid;               // coalesced
        float4 b = bp[i];
        float  s = sp[i];
        float w = b.z - b.x;
        float h = b.w - b.y;
        bool valid = (w >= MIN_SIZE) && (h >= MIN_SIZE) && (s >= SCORE_THR);
        sbox[i] = b;
        skey[i] = valid ? pack_si(s, i) : 0ULL;
    }

    // ---- init output padding: [img,0,0,0,0] rows, mask = 0 ----
    float* outr = out + (size_t)img * MAXDET * 5;
    float* outm = out + (size_t)BATCH * MAXDET * 5 + (size_t)img * MAXDET;
    for (int i = tid; i < MAXDET; i += THREADS) {
        outr[i * 5 + 0] = (float)img;
        outr[i * 5 + 1] = 0.f;
        outr[i * 5 + 2] = 0.f;
        outr[i * 5 + 3] = 0.f;
        outr[i * 5 + 4] = 0.f;
        if (write_mask) outm[i] = 0.f;
    }
    __syncthreads();

    // blocked ownership for the sort
    u64 val[EPT];
    #pragma unroll
    for (int e = 0; e < EPT; e++) val[e] = skey[base + e];

    // ================= bitonic sort (descending) =============================
    // blocked layout: idx = tid*8 + e. bits: [0:2]=e (regs),
    // [3:7]=lane bits (j=8..128 -> shfl), [8:10]=warp bits (j=256..1024 -> smem)

    // presort k=2..8 entirely in registers
    #pragma unroll
    for (int k = 2; k <= 8; k <<= 1) {
        #pragma unroll
        for (int j = k >> 1; j > 0; j >>= 1) {
            #pragma unroll
            for (int e = 0; e < EPT; e++) {
                if ((e & j) == 0) {
                    int f = e | j;
                    bool up = (((base + e) & k) == 0);
                    u64 x = val[e], y = val[f];
                    bool sw = up ? (x < y) : (x > y);
                    if (sw) { val[e] = y; val[f] = x; }
                }
            }
        }
    }

    #pragma unroll 1
    for (int kk = 16; kk <= NBOX; kk <<= 1) {
        const bool dir = ((base & kk) == 0);          // uniform over e (kk>=16)

        // --- shared stages: j in {1024, 512, 256} (warp-bit exchanges) ---
        #pragma unroll 1
        for (int j = kk >> 1; j >= 256; j >>= 1) {
            #pragma unroll
            for (int e = 0; e < EPT; e++) skey[base + e] = val[e];
            __syncthreads();
            bool iLow = ((tid & (j >> 3)) == 0);
            int pbase = base ^ j;                     // partner thread's block
            #pragma unroll
            for (int e = 0; e < EPT; e++) {
                u64 o = skey[pbase + e];
                u64 mx = val[e] > o ? val[e] : o;
                u64 mn = val[e] > o ? o : val[e];
                val[e] = (iLow == dir) ? mx : mn;
            }
            __syncthreads();
        }

        // --- shfl stages: j in {128..8} (lane-bit exchanges) ---
        {
            int jhi = (kk >> 1) > 128 ? 128 : (kk >> 1);
            #pragma unroll 1
            for (int j = jhi; j >= 8; j >>= 1) {
                int jl = j >> 3;                      // lane xor mask
                bool iLow = ((tid & jl) == 0);
                #pragma unroll
                for (int e = 0; e < EPT; e++) {
                    u64 o = __shfl_xor_sync(FULL, val[e], jl);
                    u64 mx = val[e] > o ? val[e] : o;
                    u64 mn = val[e] > o ? o : val[e];
                    val[e] = (iLow == dir) ? mx : mn;
                }
            }
        }

        // --- register tail: j = 4..1 ---
        #pragma unroll
        for (int j = 4; j > 0; j >>= 1) {
            #pragma unroll
            for (int e = 0; e < EPT; e++) {
                if ((e & j) == 0) {
                    int f = e | j;
                    u64 x = val[e], y = val[f];
                    bool sw = dir ? (x < y) : (x > y);
                    if (sw) { val[e] = y; val[f] = x; }
                }
            }
        }
    }
    // write sorted keys (rank order) to shared for the batch engine
    #pragma unroll
    for (int e = 0; e < EPT; e++) skey[base + e] = val[e];
    __syncthreads();

    // ================= lazy greedy: batch-verified walk in rank order ========
    int npicks = 0;
    int rb = 0;
    while (rb < NBOX && npicks < MAXDET) {
        // every warp stages the same 32 candidates (broadcast LDS)
        u64 kkey = skey[rb + lane];
        if (__shfl_sync(FULL, kkey, 0) == 0ULL) break;   // rank rb invalid => done

        int cidx = (int)(~(u32)kkey) & (NBOX - 1);
        float4 myb = sbox[cidx];               // candidate = lane (all warps)
        float  mya = ciou_area(myb);
        u32 vmask = __ballot_sync(FULL, kkey != 0ULL);   // identical per warp

        if (warp < 4) {
            // (b) 32x32 pairwise overlap: partner boxes via shfl from lane c
            u32 bits8 = 0;
            #pragma unroll
            for (int q = 0; q < 8; q++) {
                int c = warp * 8 + q;
                float4 ob;
                ob.x = __shfl_sync(FULL, myb.x, c);
                ob.y = __shfl_sync(FULL, myb.y, c);
                ob.z = __shfl_sync(FULL, myb.z, c);
                ob.w = __shfl_sync(FULL, myb.w, c);
                float oa = __shfl_sync(FULL, mya, c);
                bool ov = inter_of(myb, ob) > mya + oa;
                bits8 |= (ov ? 1u : 0u) << q;
            }
            smat8[lane * 4 + warp] = (unsigned char)bits8;
        } else {
            // (a) candidate vs existing picks (picks strided over warps 4-7)
            bool dead = false;
            for (int j = warp - 4; j < npicks; j += 4) {
                float4 pb = pbox[j];
                dead |= inter_of(pb, myb) > pca[j] + mya;
            }
            u32 bal = __ballot_sync(FULL, dead);
            if (lane == 0) sdead[warp - 4] = bal;
        }
        __syncthreads();

        // (c)+(d): warp 0 only — walk + append picks + write output
        if (warp == 0) {
            u32 deadP = sdead[0] | sdead[1] | sdead[2] | sdead[3];
            u32 elig  = vmask & ~deadP;

            u32 rows[32];
            #pragma unroll
            for (int j = 0; j < 32; j++) rows[j] = smat32[j];
            u32 acc = 0;
            #pragma unroll
            for (int j = 0; j < 32; j++) {
                bool take = ((elig >> j) & 1u) && ((acc & rows[j]) == 0u);
                acc |= (take ? 1u : 0u) << j;
            }
            if (lane == 0) *sacc = acc;

            if ((acc >> lane) & 1u) {          // lane == candidate
                int slot = npicks + __popc(acc & ((1u << lane) - 1u));
                if (slot < MAXDET) {
                    pbox[slot] = myb;
                    pca[slot]  = mya;
                    float* row = outr + slot * 5;
                    row[1] = myb.x; row[2] = myb.y; row[3] = myb.z; row[4] = myb.w;
                    if (write_mask) outm[slot] = 1.f;
                }
            }
        }
        __syncthreads();                       // pbox/pca/sacc visible to all

        npicks = min(npicks + __popc(*sacc), MAXDET);
        rb += 32;
    }
}

extern "C" void kernel_launch(void* const* d_in, const int* in_sizes, int n_in,
                              void* d_out, int out_size) {
    const float* boxes  = (const float*)d_in[0];   // [8,2048,4] f32
    const float* scores = (const float*)d_in[1];   // [8,2048]   f32
    float* out = (float*)d_out;
    int write_mask = (out_size >= BATCH * MAXDET * 5 + BATCH * MAXDET) ? 1 : 0;

    static int attr_done = 0;
    if (!attr_done) {
        cudaFuncSetAttribute(nms_kernel,
                             cudaFuncAttributeMaxDynamicSharedMemorySize,
                             SMEM_BYTES);
        attr_done = 1;
    }
    nms_kernel<<<BATCH, THREADS, SMEM_BYTES>>>(boxes, scores, out, write_mask);
}